// round 1
// baseline (speedup 1.0000x reference)
#include <cuda_runtime.h>
#include <math.h>

#define B_ 32
#define T_ 8
#define K_ 64
#define D_ 512
#define CIN_ 1536
#define HW_ 64
#define NT_ 256

// ---------------- scratch (device globals; no allocation) ----------------
__device__ float g_xt [NT_ * D_ * HW_];   // (n, d, s)
__device__ float g_xtT[NT_ * HW_ * D_];   // (n, s, d)
__device__ float g_wxpb[NT_ * K_ * HW_];  // (n, k, s)
__device__ float g_attv[NT_ * K_ * HW_];  // (n, k, s), n = b*T + t
__device__ float g_hs [T_ * B_ * K_ * HW_];
__device__ float g_h   [B_ * K_ * HW_];
__device__ float g_ah  [B_ * K_ * HW_];
__device__ float g_uz  [B_ * K_ * HW_];
__device__ float g_ur  [B_ * K_ * HW_];
__device__ float g_wxt0[B_ * K_ * HW_];
__device__ float g_wxtb[B_ * K_ * HW_];
__device__ float g_zb  [B_ * K_ * HW_];
__device__ float g_rh  [B_ * K_ * HW_];
__device__ float g_mean[B_ * T_ * K_];
__device__ float g_maxv[B_ * T_ * K_];
__device__ float g_alph[B_ * T_ * K_];
__device__ float g_asum[B_ * K_];
__device__ float g_vlad[B_ * K_ * D_];

// ---------------- utility ----------------
__global__ void zero_h_kernel() {
    int i = blockIdx.x * 256 + threadIdx.x;
    if (i < B_ * K_ * HW_) g_h[i] = 0.f;
}

__device__ __forceinline__ float sigmoidf_(float x) { return 1.f / (1.f + expf(-x)); }

// ---------------- GEMM 1: xt = redu_w @ x + redu_b ----------------
// C(512 x 16384) = W(512 x 1536) * X(1536 x 16384), X col = n*64+s
// 128x128 tile, BK=8, 256 threads, 8x8 micro-tile.
__global__ void __launch_bounds__(256) gemm_redu(const float* __restrict__ x,
                                                 const float* __restrict__ W,
                                                 const float* __restrict__ bias) {
    __shared__ float As[8][128];
    __shared__ float Bs[8][128];
    int tid = threadIdx.x;
    int tx = tid & 15, ty = tid >> 4;
    int d0 = blockIdx.x * 128, col0 = blockIdx.y * 128;
    float acc[8][8];
#pragma unroll
    for (int i = 0; i < 8; i++)
#pragma unroll
        for (int j = 0; j < 8; j++) acc[i][j] = 0.f;

    for (int k0 = 0; k0 < CIN_; k0 += 8) {
#pragma unroll
        for (int i = tid; i < 1024; i += 256) {
            int dd = i >> 3, kk = i & 7;
            As[kk][dd] = W[(d0 + dd) * CIN_ + k0 + kk];
        }
#pragma unroll
        for (int i = tid; i < 1024; i += 256) {
            int kk = i >> 7, j = i & 127;
            int col = col0 + j;
            Bs[kk][j] = x[(col >> 6) * (CIN_ * HW_) + (k0 + kk) * HW_ + (col & 63)];
        }
        __syncthreads();
#pragma unroll
        for (int kk = 0; kk < 8; kk++) {
            float a[8], b[8];
#pragma unroll
            for (int i = 0; i < 8; i++) a[i] = As[kk][ty * 8 + i];
#pragma unroll
            for (int j = 0; j < 8; j++) b[j] = Bs[kk][tx * 8 + j];
#pragma unroll
            for (int i = 0; i < 8; i++)
#pragma unroll
                for (int j = 0; j < 8; j++) acc[i][j] += a[i] * b[j];
        }
        __syncthreads();
    }
#pragma unroll
    for (int i = 0; i < 8; i++) {
        int d = d0 + ty * 8 + i;
        float bv = bias[d];
#pragma unroll
        for (int j = 0; j < 8; j++) {
            int col = col0 + tx * 8 + j;
            int n = col >> 6, s = col & 63;
            float v = acc[i][j] + bv;
            g_xt [n * (D_ * HW_) + d * HW_ + s] = v;
            g_xtT[n * (D_ * HW_) + s * D_  + d] = v;
        }
    }
}

// ---------------- GEMM 2: wxpb[n,k,s] = sum_d wx[k,d]*xt[n,d,s] ----------------
__global__ void __launch_bounds__(256) gemm_wx(const float* __restrict__ wx) {
    int n = blockIdx.x;
    __shared__ float As[16][64];
    __shared__ float Bs[16][64];
    int tid = threadIdx.x, tx = tid & 15, ty = tid >> 4;
    float acc[4][4];
#pragma unroll
    for (int i = 0; i < 4; i++)
#pragma unroll
        for (int j = 0; j < 4; j++) acc[i][j] = 0.f;
    const float* xb = g_xt + n * (D_ * HW_);
    for (int d0 = 0; d0 < D_; d0 += 16) {
#pragma unroll
        for (int i = tid; i < 1024; i += 256) {
            int k = i >> 4, kk = i & 15;
            As[kk][k] = wx[k * D_ + d0 + kk];
        }
#pragma unroll
        for (int i = tid; i < 1024; i += 256) {
            int kk = i >> 6, s = i & 63;
            Bs[kk][s] = xb[(d0 + kk) * HW_ + s];
        }
        __syncthreads();
#pragma unroll
        for (int kk = 0; kk < 16; kk++) {
            float a[4], b[4];
#pragma unroll
            for (int i = 0; i < 4; i++) a[i] = As[kk][ty * 4 + i];
#pragma unroll
            for (int j = 0; j < 4; j++) b[j] = Bs[kk][tx * 4 + j];
#pragma unroll
            for (int i = 0; i < 4; i++)
#pragma unroll
                for (int j = 0; j < 4; j++) acc[i][j] += a[i] * b[j];
        }
        __syncthreads();
    }
#pragma unroll
    for (int i = 0; i < 4; i++)
#pragma unroll
        for (int j = 0; j < 4; j++)
            g_wxpb[n * (K_ * HW_) + (ty * 4 + i) * HW_ + tx * 4 + j] = acc[i][j];
}

// ---------------- conv3x3 core (one 64ch 8x8 image per block, 256 threads) ----
__device__ __forceinline__ void conv3x3_core(const float* __restrict__ in,
                                             const float* __restrict__ w,
                                             float* sIn, float* sW, float acc[4][4]) {
    int tid = threadIdx.x;
    for (int i = tid; i < 4096; i += 256) sIn[i] = in[i];
    int tx = tid & 15, ty = tid >> 4;
    int y = tx >> 1, x0 = (tx & 1) * 4;
#pragma unroll
    for (int i = 0; i < 4; i++)
#pragma unroll
        for (int j = 0; j < 4; j++) acc[i][j] = 0.f;

    for (int c0 = 0; c0 < 64; c0 += 8) {
        __syncthreads();
        for (int i = tid; i < 4608; i += 256) {
            int cc = i / 576, rest = i - cc * 576;
            sW[i] = w[(rest / 9) * 576 + (c0 + cc) * 9 + (rest % 9)];
        }
        __syncthreads();
#pragma unroll
        for (int cc = 0; cc < 8; cc++) {
            const float* ip = sIn + (c0 + cc) * 64;
            float inv[3][6];
#pragma unroll
            for (int r = 0; r < 3; r++) {
                int yy = y + r - 1;
                bool yok = (yy >= 0) && (yy < 8);
#pragma unroll
                for (int q = 0; q < 6; q++) {
                    int xx = x0 + q - 1;
                    inv[r][q] = (yok && xx >= 0 && xx < 8) ? ip[yy * 8 + xx] : 0.f;
                }
            }
#pragma unroll
            for (int i2 = 0; i2 < 4; i2++) {
                const float* wp = sW + cc * 576 + (ty * 4 + i2) * 9;
#pragma unroll
                for (int r = 0; r < 3; r++)
#pragma unroll
                    for (int q2 = 0; q2 < 3; q2++) {
                        float wv = wp[r * 3 + q2];
#pragma unroll
                        for (int j = 0; j < 4; j++)
                            acc[i2][j] += wv * inv[r][q2 + j];
                    }
            }
        }
    }
}

// plain conv: out = conv(in) (+ bias)
__global__ void __launch_bounds__(256) conv_plain(const float* __restrict__ in,
                                                  const float* __restrict__ w,
                                                  const float* __restrict__ bias,
                                                  float* __restrict__ out) {
    __shared__ float sIn[4096];
    __shared__ float sW[4608];
    int n = blockIdx.x;
    float acc[4][4];
    conv3x3_core(in + n * 4096, w, sIn, sW, acc);
    int tx = threadIdx.x & 15, ty = threadIdx.x >> 4;
#pragma unroll
    for (int i = 0; i < 4; i++) {
        int k = ty * 4 + i;
        float bv = bias ? bias[k] : 0.f;
#pragma unroll
        for (int j = 0; j < 4; j++)
            out[n * 4096 + k * 64 + tx * 4 + j] = acc[i][j] + bv;
    }
}

// trio: ah = conv(h, att_h_w)+att_b ; uz = conv(h, U_z) ; ur = conv(h, U_r)
__global__ void __launch_bounds__(256) conv_trio(const float* __restrict__ w_ah,
                                                 const float* __restrict__ b_ah,
                                                 const float* __restrict__ w_uz,
                                                 const float* __restrict__ w_ur) {
    __shared__ float sIn[4096];
    __shared__ float sW[4608];
    int n = blockIdx.x;
    int which = blockIdx.y;
    const float* w = (which == 0) ? w_ah : (which == 1) ? w_uz : w_ur;
    float* out = (which == 0) ? g_ah : (which == 1) ? g_uz : g_ur;
    float acc[4][4];
    conv3x3_core(g_h + n * 4096, w, sIn, sW, acc);
    int tx = threadIdx.x & 15, ty = threadIdx.x >> 4;
#pragma unroll
    for (int i = 0; i < 4; i++) {
        int k = ty * 4 + i;
        float bv = (which == 0) ? b_ah[k] : 0.f;
#pragma unroll
        for (int j = 0; j < 4; j++)
            out[n * 4096 + k * 64 + tx * 4 + j] = acc[i][j] + bv;
    }
}

// share conv + gate elementwise: wxt = conv(wxt0)+b ; z, r ; rh = r*h
__global__ void __launch_bounds__(256) conv_share(const float* __restrict__ w,
                                                  const float* __restrict__ bias) {
    __shared__ float sIn[4096];
    __shared__ float sW[4608];
    int n = blockIdx.x;
    float acc[4][4];
    conv3x3_core(g_wxt0 + n * 4096, w, sIn, sW, acc);
    int tx = threadIdx.x & 15, ty = threadIdx.x >> 4;
#pragma unroll
    for (int i = 0; i < 4; i++) {
        int k = ty * 4 + i;
        float bv = bias[k];
#pragma unroll
        for (int j = 0; j < 4; j++) {
            int e = n * 4096 + k * 64 + tx * 4 + j;
            float wxt = acc[i][j] + bv;
            float z = sigmoidf_(wxt + g_uz[e]);
            float r = sigmoidf_(wxt + g_ur[e]);
            g_wxtb[e] = wxt;
            g_zb[e] = z;
            g_rh[e] = r * g_h[e];
        }
    }
}

// final conv + GRU update: hh = tanh(wxt + conv(rh,U_h)); h = (1-z)hh + z h; hs[t]=h
__global__ void __launch_bounds__(256) conv_final(const float* __restrict__ w, int t) {
    __shared__ float sIn[4096];
    __shared__ float sW[4608];
    int n = blockIdx.x;
    float acc[4][4];
    conv3x3_core(g_rh + n * 4096, w, sIn, sW, acc);
    int tx = threadIdx.x & 15, ty = threadIdx.x >> 4;
#pragma unroll
    for (int i = 0; i < 4; i++) {
        int k = ty * 4 + i;
#pragma unroll
        for (int j = 0; j < 4; j++) {
            int e = n * 4096 + k * 64 + tx * 4 + j;
            float hh = tanhf(g_wxtb[e] + acc[i][j]);
            float z = g_zb[e];
            float hn = (1.f - z) * hh + z * g_h[e];
            g_h[e] = hn;
            g_hs[((t * B_ + n) * K_ + k) * 64 + tx * 4 + j] = hn;
        }
    }
}

// ---------------- per-step stats: mean/max over HW of relu(attv + ah) ---------
__global__ void __launch_bounds__(256) stats_kernel() {
    int gw = blockIdx.x * 8 + (threadIdx.x >> 5);
    int lane = threadIdx.x & 31;
    int b = gw >> 9;
    int rem = gw & 511;        // t*64+k
    int t = rem >> 6, k = rem & 63;
    const float* av = g_attv + ((b * T_ + t) * K_ + k) * 64;
    const float* ah = g_ah + (b * K_ + k) * 64;
    float v0 = fmaxf(av[lane] + ah[lane], 0.f);
    float v1 = fmaxf(av[lane + 32] + ah[lane + 32], 0.f);
    float sum = v0 + v1;
    float mx = fmaxf(v0, v1);
#pragma unroll
    for (int o = 16; o; o >>= 1) {
        sum += __shfl_xor_sync(0xffffffffu, sum, o);
        mx = fmaxf(mx, __shfl_xor_sync(0xffffffffu, mx, o));
    }
    if (lane == 0) {
        g_mean[b * 512 + rem] = sum * (1.f / 64.f);
        g_maxv[b * 512 + rem] = mx;
    }
}

// ---------------- fc + tanh + softmax over T -> alphas ----------------
__global__ void __launch_bounds__(256) fc_softmax(const float* __restrict__ fc1,
                                                  const float* __restrict__ fc2) {
    int b = blockIdx.x;
    __shared__ float sm[512], sx[512], sh[64], se[512];
    int tid = threadIdx.x;
    for (int i = tid; i < 512; i += 256) {
        sm[i] = g_mean[b * 512 + i];
        sx[i] = g_maxv[b * 512 + i];
    }
    __syncthreads();
    int warp = tid >> 5, lane = tid & 31;
#pragma unroll
    for (int q = 0; q < 8; q++) {
        int dd = warp * 8 + q;
        const float* src = (dd < 32) ? sm : sx;
        const float* wrow = fc1 + (dd & 31) * 512;
        float sum = 0.f;
        for (int i = lane; i < 512; i += 32) sum += src[i] * wrow[i];
#pragma unroll
        for (int o = 16; o; o >>= 1) sum += __shfl_xor_sync(0xffffffffu, sum, o);
        if (lane == 0) sh[dd] = fmaxf(sum, 0.f);
    }
    __syncthreads();
#pragma unroll
    for (int rep = 0; rep < 2; rep++) {
        int o = tid + rep * 256;
        const float* w2 = fc2 + o * 32;
        float v = 0.f;
#pragma unroll
        for (int j = 0; j < 32; j++) v += w2[j] * (sh[j] + sh[j + 32]);
        se[o] = expf(tanhf(v));
    }
    __syncthreads();
    if (tid < 64) {
        float den = 0.f;
#pragma unroll
        for (int t = 0; t < T_; t++) den += se[t * 64 + tid];
        if (den == 0.f) den = 1.f;
        float inv = 1.f / den;
#pragma unroll
        for (int t = 0; t < T_; t++)
            g_alph[b * 512 + t * 64 + tid] = se[t * 64 + tid] * inv;
    }
}

// ---------------- weighted sum over T: wxt0 ----------------
__global__ void __launch_bounds__(256) wxt0_kernel() {
    int b = blockIdx.x;
    int tid = threadIdx.x;
#pragma unroll
    for (int ii = 0; ii < 16; ii++) {
        int idx = tid + ii * 256;    // k*64 + s
        int k = idx >> 6;
        float acc = 0.f;
#pragma unroll
        for (int t = 0; t < T_; t++)
            acc += g_alph[b * 512 + t * 64 + k] * g_wxpb[(b * T_ + t) * 4096 + idx];
        g_wxt0[b * 4096 + idx] = acc;
    }
}

// ---------------- a_sum[b,k] = sum_{t,s} hs ----------------
__global__ void __launch_bounds__(256) asum_kernel() {
    int b = blockIdx.x;
    int tid = threadIdx.x;
    int k = tid >> 2, part = tid & 3;
    float sum = 0.f;
#pragma unroll
    for (int t = 0; t < T_; t++) {
        const float* p = g_hs + ((t * B_ + b) * K_ + k) * 64 + part * 16;
#pragma unroll
        for (int s = 0; s < 16; s++) sum += p[s];
    }
    sum += __shfl_down_sync(0xffffffffu, sum, 2);
    sum += __shfl_down_sync(0xffffffffu, sum, 1);
    if (part == 0) g_asum[b * K_ + k] = sum;
}

// ---------------- VLAD GEMM: per b, C(64x512) over ts(512), minus asum*centers --
__global__ void __launch_bounds__(256) vlad_gemm(const float* __restrict__ centers) {
    int b = blockIdx.y;
    int d0 = blockIdx.x * 64;
    __shared__ float As[16][64];
    __shared__ float Bs[16][64];
    int tid = threadIdx.x, tx = tid & 15, ty = tid >> 4;
    float acc[4][4];
#pragma unroll
    for (int i = 0; i < 4; i++)
#pragma unroll
        for (int j = 0; j < 4; j++) acc[i][j] = 0.f;

    for (int ts0 = 0; ts0 < 512; ts0 += 16) {
        int t = ts0 >> 6, s0 = ts0 & 63;
        const float* hsb = g_hs + ((t * B_ + b) * K_) * 64 + s0;          // + k*64 + kk
        const float* xtb = g_xtT + (b * T_ + t) * (HW_ * D_) + s0 * D_ + d0; // + kk*512 + d
#pragma unroll
        for (int i = tid; i < 1024; i += 256) {
            int k = i >> 4, kk = i & 15;
            As[kk][k] = hsb[k * 64 + kk];
        }
#pragma unroll
        for (int i = tid; i < 1024; i += 256) {
            int kk = i >> 6, dd = i & 63;
            Bs[kk][dd] = xtb[kk * D_ + dd];
        }
        __syncthreads();
#pragma unroll
        for (int kk = 0; kk < 16; kk++) {
            float a[4], bb[4];
#pragma unroll
            for (int i = 0; i < 4; i++) a[i] = As[kk][ty * 4 + i];
#pragma unroll
            for (int j = 0; j < 4; j++) bb[j] = Bs[kk][tx * 4 + j];
#pragma unroll
            for (int i = 0; i < 4; i++)
#pragma unroll
                for (int j = 0; j < 4; j++) acc[i][j] += a[i] * bb[j];
        }
        __syncthreads();
    }
#pragma unroll
    for (int i = 0; i < 4; i++) {
        int k = ty * 4 + i;
        float as = g_asum[b * K_ + k];
#pragma unroll
        for (int j = 0; j < 4; j++) {
            int d = d0 + tx * 4 + j;
            g_vlad[b * (K_ * D_) + k * D_ + d] = acc[i][j] - as * centers[k * D_ + d];
        }
    }
}

// ---------------- two-level normalization ----------------
__global__ void __launch_bounds__(256) norm_kernel(float* __restrict__ out) {
    int b = blockIdx.x, tid = threadIdx.x;
    int warp = tid >> 5, lane = tid & 31;
    __shared__ float sss[64];
    __shared__ float sinv[64];
    __shared__ float sbinv;
    const float* v = g_vlad + b * (K_ * D_);
#pragma unroll
    for (int q = 0; q < 8; q++) {
        int k = warp * 8 + q;
        const float* row = v + k * D_;
        float ss = 0.f;
        for (int i = lane; i < D_; i += 32) { float x = row[i]; ss += x * x; }
#pragma unroll
        for (int o = 16; o; o >>= 1) ss += __shfl_xor_sync(0xffffffffu, ss, o);
        if (lane == 0) sss[k] = ss;
    }
    __syncthreads();
    if (tid < 64) sinv[tid] = 1.f / fmaxf(sqrtf(sss[tid]), 1e-12f);
    __syncthreads();
    if (tid == 0) {
        float tot = 0.f;
        for (int k = 0; k < 64; k++) tot += sss[k] * sinv[k] * sinv[k];
        sbinv = 1.f / fmaxf(sqrtf(tot), 1e-12f);
    }
    __syncthreads();
    float bi = sbinv;
    for (int i = tid; i < K_ * D_; i += 256)
        out[b * (K_ * D_) + i] = v[i] * sinv[i >> 9] * bi;
}

// ---------------- launcher ----------------
extern "C" void kernel_launch(void* const* d_in, const int* in_sizes, int n_in,
                              void* d_out, int out_size) {
    const float* x       = (const float*)d_in[0];
    const float* redu_w  = (const float*)d_in[1];
    const float* redu_b  = (const float*)d_in[2];
    const float* w_x     = (const float*)d_in[3];
    const float* att_x   = (const float*)d_in[4];
    const float* att_h_w = (const float*)d_in[5];
    const float* att_b   = (const float*)d_in[6];
    const float* share_w = (const float*)d_in[7];
    const float* share_b = (const float*)d_in[8];
    const float* U_r     = (const float*)d_in[9];
    const float* U_z     = (const float*)d_in[10];
    const float* U_h     = (const float*)d_in[11];
    const float* centers = (const float*)d_in[12];
    const float* fc1_w   = (const float*)d_in[13];
    const float* fc2_w   = (const float*)d_in[14];
    float* out = (float*)d_out;

    zero_h_kernel<<<(B_ * K_ * HW_ + 255) / 256, 256>>>();

    gemm_redu<<<dim3(4, 128), 256>>>(x, redu_w, redu_b);
    gemm_wx<<<NT_, 256>>>(w_x);

    // att_v = conv3x3(wxpb, att_x), no bias
    {
        float* attv_ptr = nullptr;
        cudaGetSymbolAddress((void**)&attv_ptr, g_attv);
        float* wxpb_ptr = nullptr;
        cudaGetSymbolAddress((void**)&wxpb_ptr, g_wxpb);
        conv_plain<<<NT_, 256>>>(wxpb_ptr, att_x, nullptr, attv_ptr);
    }

    for (int t = 0; t < T_; t++) {
        conv_trio<<<dim3(B_, 3), 256>>>(att_h_w, att_b, U_z, U_r);
        stats_kernel<<<(B_ * T_ * K_) / 8, 256>>>();
        fc_softmax<<<B_, 256>>>(fc1_w, fc2_w);
        wxt0_kernel<<<B_, 256>>>();
        conv_share<<<B_, 256>>>(share_w, share_b);
        conv_final<<<B_, 256>>>(U_h, t);
    }

    asum_kernel<<<B_, 256>>>();
    vlad_gemm<<<dim3(8, B_), 256>>>(centers);
    norm_kernel<<<B_, 256>>>(out);
}

// round 3
// speedup vs baseline: 1.3551x; 1.3551x over previous
#include <cuda_runtime.h>
#include <cuda_fp16.h>
#include <math.h>
#include <stdint.h>

#define B_ 32
#define T_ 8
#define K_ 64
#define D_ 512
#define CIN_ 1536
#define HW_ 64
#define NT_ 256

// ---------------- scratch (device globals; no allocation) ----------------
__device__ float g_xt [NT_ * D_ * HW_];   // (n, d, s)
__device__ float g_xtT[NT_ * HW_ * D_];   // (n, s, d)
__device__ __half g_xh[(size_t)NT_ * HW_ * CIN_]; // (col=(n*64+s), cin) K-major fp16
__device__ __half g_wh[D_ * CIN_];        // (d, cin) K-major fp16
__device__ float g_wxpb[NT_ * K_ * HW_];  // (n, k, s)
__device__ float g_attv[NT_ * K_ * HW_];  // (n, k, s)
__device__ float g_hs [T_ * B_ * K_ * HW_];
__device__ float g_h   [B_ * K_ * HW_];
__device__ float g_ah  [B_ * K_ * HW_];
__device__ float g_uz  [B_ * K_ * HW_];
__device__ float g_ur  [B_ * K_ * HW_];
__device__ float g_wxt0[B_ * K_ * HW_];
__device__ float g_wxtb[B_ * K_ * HW_];
__device__ float g_zb  [B_ * K_ * HW_];
__device__ float g_rh  [B_ * K_ * HW_];
__device__ float g_mean[B_ * T_ * K_];
__device__ float g_maxv[B_ * T_ * K_];
__device__ float g_alph[B_ * T_ * K_];
__device__ float g_asum[B_ * K_];
__device__ float g_vlad[B_ * K_ * D_];

// ---------------- utility ----------------
__global__ void zero_h_kernel() {
    int i = blockIdx.x * 256 + threadIdx.x;
    if (i < B_ * K_ * HW_) g_h[i] = 0.f;
}
__device__ __forceinline__ float sigmoidf_(float x) { return 1.f / (1.f + expf(-x)); }

// ---------------- convert W to fp16 ----------------
__global__ void convert_w(const float* __restrict__ W) {
    int i = blockIdx.x * 1024 + threadIdx.x;
    if (i < D_ * CIN_) g_wh[i] = __float2half(W[i]);
}

// ---------------- transpose x (n,cin,s) fp32 -> xh[(n*64+s)][cin] fp16 -------
__global__ void __launch_bounds__(256) transpose_x(const float* __restrict__ x) {
    __shared__ float sm[64 * 65];
    int n = blockIdx.y, c0 = blockIdx.x * 64;
    const float* src = x + ((size_t)n * CIN_ + c0) * 64;
    for (int i = threadIdx.x; i < 4096; i += 256) {
        int ci = i >> 6, s = i & 63;
        sm[ci * 65 + s] = src[i];
    }
    __syncthreads();
#pragma unroll
    for (int rep = 0; rep < 8; rep++) {
        int idx = rep * 256 + threadIdx.x;   // 0..2047
        int s = idx >> 5, cp = idx & 31, ci = cp * 2;
        __half2 h = __floats2half2_rn(sm[ci * 65 + s], sm[(ci + 1) * 65 + s]);
        *(__half2*)(g_xh + ((size_t)(n * 64 + s)) * CIN_ + c0 + ci) = h;
    }
}

// ---------------- HMMA GEMM: xt = W @ x + b  (mma.sync m16n8k16 f16->f32) ----
// D[m=col(0..16383), n=d(0..511)] = sum_cin xh[col,cin] * wh[d,cin]
// CTA tile 128x128xK32, 8 warps (2x4), warp tile 64x32.
#define GPAD 40   // halves per smem row (32 data + 8 pad)
#define EPAD 67   // floats per epilogue smem row

__device__ __forceinline__ void mma16816(float* c, const uint32_t* a, const uint32_t* b) {
    asm volatile(
        "mma.sync.aligned.m16n8k16.row.col.f32.f16.f16.f32 "
        "{%0,%1,%2,%3}, {%4,%5,%6,%7}, {%8,%9}, {%0,%1,%2,%3};"
        : "+f"(c[0]), "+f"(c[1]), "+f"(c[2]), "+f"(c[3])
        : "r"(a[0]), "r"(a[1]), "r"(a[2]), "r"(a[3]), "r"(b[0]), "r"(b[1]));
}

__global__ void __launch_bounds__(256) gemm_redu_mma(const float* __restrict__ bias) {
    __shared__ __align__(16) char sbuf[128 * EPAD * 4 > 2 * 128 * GPAD * 2
                                           ? 128 * EPAD * 4
                                           : 2 * 128 * GPAD * 2];
    __half* As = (__half*)sbuf;                       // [128][GPAD]
    __half* Bs = (__half*)(sbuf + 128 * GPAD * 2);    // [128][GPAD]
    float* sEp = (float*)sbuf;                        // [128][EPAD]

    int tid = threadIdx.x;
    int wid = tid >> 5, lane = tid & 31;
    int warp_m = wid >> 2, warp_n = wid & 3;
    int moff = warp_m * 64, noff = warp_n * 32;
    int m0 = blockIdx.x * 128, n0 = blockIdx.y * 128;
    int lr = lane >> 2, lc = (lane & 3) * 2;

    float acc[4][4][4];
#pragma unroll
    for (int i = 0; i < 4; i++)
#pragma unroll
        for (int j = 0; j < 4; j++)
#pragma unroll
            for (int q = 0; q < 4; q++) acc[i][j][q] = 0.f;

    for (int k0 = 0; k0 < CIN_; k0 += 32) {
        // load A tile 128x32 halves, B tile 128x32 halves (uint4 = 8 halves)
#pragma unroll
        for (int i = tid; i < 512; i += 256) {
            int r = i >> 2, c8 = i & 3;
            uint4 va = *(const uint4*)(g_xh + (size_t)(m0 + r) * CIN_ + k0 + c8 * 8);
            *(uint4*)(As + r * GPAD + c8 * 8) = va;
            uint4 vb = *(const uint4*)(g_wh + (size_t)(n0 + r) * CIN_ + k0 + c8 * 8);
            *(uint4*)(Bs + r * GPAD + c8 * 8) = vb;
        }
        __syncthreads();
#pragma unroll
        for (int ks = 0; ks < 2; ks++) {
            int kb = ks * 16 + lc;
            uint32_t afr[4][4], bfr[4][2];
#pragma unroll
            for (int mf = 0; mf < 4; mf++) {
                int row = moff + mf * 16 + lr;
                afr[mf][0] = *(const uint32_t*)(As + row * GPAD + kb);
                afr[mf][1] = *(const uint32_t*)(As + (row + 8) * GPAD + kb);
                afr[mf][2] = *(const uint32_t*)(As + row * GPAD + kb + 8);
                afr[mf][3] = *(const uint32_t*)(As + (row + 8) * GPAD + kb + 8);
            }
#pragma unroll
            for (int nf = 0; nf < 4; nf++) {
                int rn = noff + nf * 8 + lr;
                bfr[nf][0] = *(const uint32_t*)(Bs + rn * GPAD + kb);
                bfr[nf][1] = *(const uint32_t*)(Bs + rn * GPAD + kb + 8);
            }
#pragma unroll
            for (int mf = 0; mf < 4; mf++)
#pragma unroll
                for (int nf = 0; nf < 4; nf++)
                    mma16816(acc[mf][nf], afr[mf], bfr[nf]);
        }
        __syncthreads();
    }

    // epilogue: two 64-d slabs through smem, coalesced stores to g_xt and g_xtT
#pragma unroll 1
    for (int slab = 0; slab < 2; slab++) {
        __syncthreads();
        if ((warp_n >> 1) == slab) {
            int ncol = (warp_n & 1) * 32;
#pragma unroll
            for (int mf = 0; mf < 4; mf++) {
                int row = moff + mf * 16 + lr;
#pragma unroll
                for (int nf = 0; nf < 4; nf++) {
                    int col = ncol + nf * 8 + lc;
                    sEp[row * EPAD + col]           = acc[mf][nf][0];
                    sEp[row * EPAD + col + 1]       = acc[mf][nf][1];
                    sEp[(row + 8) * EPAD + col]     = acc[mf][nf][2];
                    sEp[(row + 8) * EPAD + col + 1] = acc[mf][nf][3];
                }
            }
        }
        __syncthreads();
        int dbase = n0 + slab * 64;
        // g_xt: (n, d, s) — coalesce over m (=ss)
#pragma unroll
        for (int idx = tid; idx < 8192; idx += 256) {
            int m = idx & 127, dn = idx >> 7;
            int col = m0 + m, nn = col >> 6, ss = col & 63;
            int d = dbase + dn;
            g_xt[(size_t)nn * (D_ * HW_) + d * 64 + ss] = sEp[m * EPAD + dn] + bias[d];
        }
        // g_xtT: (n, s, d) — coalesce over d
#pragma unroll
        for (int idx = tid; idx < 8192; idx += 256) {
            int dn = idx & 63, m = idx >> 6;
            int col = m0 + m, nn = col >> 6, ss = col & 63;
            int d = dbase + dn;
            g_xtT[(size_t)nn * (HW_ * D_) + ss * 512 + d] = sEp[m * EPAD + dn] + bias[d];
        }
    }
}

// ---------------- GEMM 2: wxpb[n,k,s] = sum_d wx[k,d]*xt[n,d,s] ----------------
__global__ void __launch_bounds__(256) gemm_wx(const float* __restrict__ wx) {
    int n = blockIdx.x;
    __shared__ float As[16][64];
    __shared__ float Bs[16][64];
    int tid = threadIdx.x, tx = tid & 15, ty = tid >> 4;
    float acc[4][4];
#pragma unroll
    for (int i = 0; i < 4; i++)
#pragma unroll
        for (int j = 0; j < 4; j++) acc[i][j] = 0.f;
    const float* xb = g_xt + (size_t)n * (D_ * HW_);
    for (int d0 = 0; d0 < D_; d0 += 16) {
#pragma unroll
        for (int i = tid; i < 1024; i += 256) {
            int k = i >> 4, kk = i & 15;
            As[kk][k] = wx[k * D_ + d0 + kk];
        }
#pragma unroll
        for (int i = tid; i < 1024; i += 256) {
            int kk = i >> 6, s = i & 63;
            Bs[kk][s] = xb[(d0 + kk) * HW_ + s];
        }
        __syncthreads();
#pragma unroll
        for (int kk = 0; kk < 16; kk++) {
            float a[4], b[4];
#pragma unroll
            for (int i = 0; i < 4; i++) a[i] = As[kk][ty * 4 + i];
#pragma unroll
            for (int j = 0; j < 4; j++) b[j] = Bs[kk][tx * 4 + j];
#pragma unroll
            for (int i = 0; i < 4; i++)
#pragma unroll
                for (int j = 0; j < 4; j++) acc[i][j] += a[i] * b[j];
        }
        __syncthreads();
    }
#pragma unroll
    for (int i = 0; i < 4; i++)
#pragma unroll
        for (int j = 0; j < 4; j++)
            g_wxpb[n * (K_ * HW_) + (ty * 4 + i) * HW_ + tx * 4 + j] = acc[i][j];
}

// ---------------- conv3x3 core (one 64ch 8x8 image per block, 256 threads) ----
__device__ __forceinline__ void conv3x3_core(const float* __restrict__ in,
                                             const float* __restrict__ w,
                                             float* sIn, float* sW, float acc[4][4]) {
    int tid = threadIdx.x;
    for (int i = tid; i < 4096; i += 256) sIn[i] = in[i];
    int tx = tid & 15, ty = tid >> 4;
    int y = tx >> 1, x0 = (tx & 1) * 4;
#pragma unroll
    for (int i = 0; i < 4; i++)
#pragma unroll
        for (int j = 0; j < 4; j++) acc[i][j] = 0.f;

    for (int c0 = 0; c0 < 64; c0 += 8) {
        __syncthreads();
        for (int i = tid; i < 4608; i += 256) {
            int cc = i / 576, rest = i - cc * 576;
            sW[i] = w[(rest / 9) * 576 + (c0 + cc) * 9 + (rest % 9)];
        }
        __syncthreads();
#pragma unroll
        for (int cc = 0; cc < 8; cc++) {
            const float* ip = sIn + (c0 + cc) * 64;
            float inv[3][6];
#pragma unroll
            for (int r = 0; r < 3; r++) {
                int yy = y + r - 1;
                bool yok = (yy >= 0) && (yy < 8);
#pragma unroll
                for (int q = 0; q < 6; q++) {
                    int xx = x0 + q - 1;
                    inv[r][q] = (yok && xx >= 0 && xx < 8) ? ip[yy * 8 + xx] : 0.f;
                }
            }
#pragma unroll
            for (int i2 = 0; i2 < 4; i2++) {
                const float* wp = sW + cc * 576 + (ty * 4 + i2) * 9;
#pragma unroll
                for (int r = 0; r < 3; r++)
#pragma unroll
                    for (int q2 = 0; q2 < 3; q2++) {
                        float wv = wp[r * 3 + q2];
#pragma unroll
                        for (int j = 0; j < 4; j++)
                            acc[i2][j] += wv * inv[r][q2 + j];
                    }
            }
        }
    }
}

__global__ void __launch_bounds__(256) conv_plain(const float* __restrict__ in,
                                                  const float* __restrict__ w,
                                                  const float* __restrict__ bias,
                                                  float* __restrict__ out) {
    __shared__ float sIn[4096];
    __shared__ float sW[4608];
    int n = blockIdx.x;
    float acc[4][4];
    conv3x3_core(in + n * 4096, w, sIn, sW, acc);
    int tx = threadIdx.x & 15, ty = threadIdx.x >> 4;
#pragma unroll
    for (int i = 0; i < 4; i++) {
        int k = ty * 4 + i;
        float bv = bias ? bias[k] : 0.f;
#pragma unroll
        for (int j = 0; j < 4; j++)
            out[n * 4096 + k * 64 + tx * 4 + j] = acc[i][j] + bv;
    }
}

__global__ void __launch_bounds__(256) conv_trio(const float* __restrict__ w_ah,
                                                 const float* __restrict__ b_ah,
                                                 const float* __restrict__ w_uz,
                                                 const float* __restrict__ w_ur) {
    __shared__ float sIn[4096];
    __shared__ float sW[4608];
    int n = blockIdx.x;
    int which = blockIdx.y;
    const float* w = (which == 0) ? w_ah : (which == 1) ? w_uz : w_ur;
    float* out = (which == 0) ? g_ah : (which == 1) ? g_uz : g_ur;
    float acc[4][4];
    conv3x3_core(g_h + n * 4096, w, sIn, sW, acc);
    int tx = threadIdx.x & 15, ty = threadIdx.x >> 4;
#pragma unroll
    for (int i = 0; i < 4; i++) {
        int k = ty * 4 + i;
        float bv = (which == 0) ? b_ah[k] : 0.f;
#pragma unroll
        for (int j = 0; j < 4; j++)
            out[n * 4096 + k * 64 + tx * 4 + j] = acc[i][j] + bv;
    }
}

__global__ void __launch_bounds__(256) conv_share(const float* __restrict__ w,
                                                  const float* __restrict__ bias) {
    __shared__ float sIn[4096];
    __shared__ float sW[4608];
    int n = blockIdx.x;
    float acc[4][4];
    conv3x3_core(g_wxt0 + n * 4096, w, sIn, sW, acc);
    int tx = threadIdx.x & 15, ty = threadIdx.x >> 4;
#pragma unroll
    for (int i = 0; i < 4; i++) {
        int k = ty * 4 + i;
        float bv = bias[k];
#pragma unroll
        for (int j = 0; j < 4; j++) {
            int e = n * 4096 + k * 64 + tx * 4 + j;
            float wxt = acc[i][j] + bv;
            float z = sigmoidf_(wxt + g_uz[e]);
            float r = sigmoidf_(wxt + g_ur[e]);
            g_wxtb[e] = wxt;
            g_zb[e] = z;
            g_rh[e] = r * g_h[e];
        }
    }
}

__global__ void __launch_bounds__(256) conv_final(const float* __restrict__ w, int t) {
    __shared__ float sIn[4096];
    __shared__ float sW[4608];
    int n = blockIdx.x;
    float acc[4][4];
    conv3x3_core(g_rh + n * 4096, w, sIn, sW, acc);
    int tx = threadIdx.x & 15, ty = threadIdx.x >> 4;
#pragma unroll
    for (int i = 0; i < 4; i++) {
        int k = ty * 4 + i;
#pragma unroll
        for (int j = 0; j < 4; j++) {
            int e = n * 4096 + k * 64 + tx * 4 + j;
            float hh = tanhf(g_wxtb[e] + acc[i][j]);
            float z = g_zb[e];
            float hn = (1.f - z) * hh + z * g_h[e];
            g_h[e] = hn;
            g_hs[((t * B_ + n) * K_ + k) * 64 + tx * 4 + j] = hn;
        }
    }
}

// ---------------- per-step stats: mean/max over HW of relu(attv + ah) ---------
__global__ void __launch_bounds__(256) stats_kernel() {
    int gw = blockIdx.x * 8 + (threadIdx.x >> 5);
    int lane = threadIdx.x & 31;
    int b = gw >> 9;
    int rem = gw & 511;
    int t = rem >> 6, k = rem & 63;
    const float* av = g_attv + ((b * T_ + t) * K_ + k) * 64;
    const float* ah = g_ah + (b * K_ + k) * 64;
    float v0 = fmaxf(av[lane] + ah[lane], 0.f);
    float v1 = fmaxf(av[lane + 32] + ah[lane + 32], 0.f);
    float sum = v0 + v1;
    float mx = fmaxf(v0, v1);
#pragma unroll
    for (int o = 16; o; o >>= 1) {
        sum += __shfl_xor_sync(0xffffffffu, sum, o);
        mx = fmaxf(mx, __shfl_xor_sync(0xffffffffu, mx, o));
    }
    if (lane == 0) {
        g_mean[b * 512 + rem] = sum * (1.f / 64.f);
        g_maxv[b * 512 + rem] = mx;
    }
}

// ---------------- fc + tanh + softmax over T -> alphas ----------------
__global__ void __launch_bounds__(256) fc_softmax(const float* __restrict__ fc1,
                                                  const float* __restrict__ fc2) {
    int b = blockIdx.x;
    __shared__ float sm[512], sx[512], sh[64], se[512];
    int tid = threadIdx.x;
    for (int i = tid; i < 512; i += 256) {
        sm[i] = g_mean[b * 512 + i];
        sx[i] = g_maxv[b * 512 + i];
    }
    __syncthreads();
    int warp = tid >> 5, lane = tid & 31;
#pragma unroll
    for (int q = 0; q < 8; q++) {
        int dd = warp * 8 + q;
        const float* src = (dd < 32) ? sm : sx;
        const float* wrow = fc1 + (dd & 31) * 512;
        float sum = 0.f;
        for (int i = lane; i < 512; i += 32) sum += src[i] * wrow[i];
#pragma unroll
        for (int o = 16; o; o >>= 1) sum += __shfl_xor_sync(0xffffffffu, sum, o);
        if (lane == 0) sh[dd] = fmaxf(sum, 0.f);
    }
    __syncthreads();
#pragma unroll
    for (int rep = 0; rep < 2; rep++) {
        int o = tid + rep * 256;
        const float* w2 = fc2 + o * 32;
        float v = 0.f;
#pragma unroll
        for (int j = 0; j < 32; j++) v += w2[j] * (sh[j] + sh[j + 32]);
        se[o] = expf(tanhf(v));
    }
    __syncthreads();
    if (tid < 64) {
        float den = 0.f;
#pragma unroll
        for (int t = 0; t < T_; t++) den += se[t * 64 + tid];
        if (den == 0.f) den = 1.f;
        float inv = 1.f / den;
#pragma unroll
        for (int t = 0; t < T_; t++)
            g_alph[b * 512 + t * 64 + tid] = se[t * 64 + tid] * inv;
    }
}

// ---------------- weighted sum over T: wxt0 ----------------
__global__ void __launch_bounds__(256) wxt0_kernel() {
    int b = blockIdx.x;
    int tid = threadIdx.x;
#pragma unroll
    for (int ii = 0; ii < 16; ii++) {
        int idx = tid + ii * 256;
        int k = idx >> 6;
        float acc = 0.f;
#pragma unroll
        for (int t = 0; t < T_; t++)
            acc += g_alph[b * 512 + t * 64 + k] * g_wxpb[(b * T_ + t) * 4096 + idx];
        g_wxt0[b * 4096 + idx] = acc;
    }
}

// ---------------- a_sum[b,k] = sum_{t,s} hs ----------------
__global__ void __launch_bounds__(256) asum_kernel() {
    int b = blockIdx.x;
    int tid = threadIdx.x;
    int k = tid >> 2, part = tid & 3;
    float sum = 0.f;
#pragma unroll
    for (int t = 0; t < T_; t++) {
        const float* p = g_hs + ((t * B_ + b) * K_ + k) * 64 + part * 16;
#pragma unroll
        for (int s = 0; s < 16; s++) sum += p[s];
    }
    sum += __shfl_down_sync(0xffffffffu, sum, 2);
    sum += __shfl_down_sync(0xffffffffu, sum, 1);
    if (part == 0) g_asum[b * K_ + k] = sum;
}

// ---------------- VLAD GEMM ----------------
__global__ void __launch_bounds__(256) vlad_gemm(const float* __restrict__ centers) {
    int b = blockIdx.y;
    int d0 = blockIdx.x * 64;
    __shared__ float As[16][64];
    __shared__ float Bs[16][64];
    int tid = threadIdx.x, tx = tid & 15, ty = tid >> 4;
    float acc[4][4];
#pragma unroll
    for (int i = 0; i < 4; i++)
#pragma unroll
        for (int j = 0; j < 4; j++) acc[i][j] = 0.f;

    for (int ts0 = 0; ts0 < 512; ts0 += 16) {
        int t = ts0 >> 6, s0 = ts0 & 63;
        const float* hsb = g_hs + ((t * B_ + b) * K_) * 64 + s0;
        const float* xtb = g_xtT + (size_t)(b * T_ + t) * (HW_ * D_) + s0 * D_ + d0;
#pragma unroll
        for (int i = tid; i < 1024; i += 256) {
            int k = i >> 4, kk = i & 15;
            As[kk][k] = hsb[k * 64 + kk];
        }
#pragma unroll
        for (int i = tid; i < 1024; i += 256) {
            int kk = i >> 6, dd = i & 63;
            Bs[kk][dd] = xtb[kk * D_ + dd];
        }
        __syncthreads();
#pragma unroll
        for (int kk = 0; kk < 16; kk++) {
            float a[4], bb[4];
#pragma unroll
            for (int i = 0; i < 4; i++) a[i] = As[kk][ty * 4 + i];
#pragma unroll
            for (int j = 0; j < 4; j++) bb[j] = Bs[kk][tx * 4 + j];
#pragma unroll
            for (int i = 0; i < 4; i++)
#pragma unroll
                for (int j = 0; j < 4; j++) acc[i][j] += a[i] * bb[j];
        }
        __syncthreads();
    }
#pragma unroll
    for (int i = 0; i < 4; i++) {
        int k = ty * 4 + i;
        float as = g_asum[b * K_ + k];
#pragma unroll
        for (int j = 0; j < 4; j++) {
            int d = d0 + tx * 4 + j;
            g_vlad[b * (K_ * D_) + k * D_ + d] = acc[i][j] - as * centers[k * D_ + d];
        }
    }
}

// ---------------- two-level normalization ----------------
__global__ void __launch_bounds__(256) norm_kernel(float* __restrict__ out) {
    int b = blockIdx.x, tid = threadIdx.x;
    int warp = tid >> 5, lane = tid & 31;
    __shared__ float sss[64];
    __shared__ float sinv[64];
    __shared__ float sbinv;
    const float* v = g_vlad + b * (K_ * D_);
#pragma unroll
    for (int q = 0; q < 8; q++) {
        int k = warp * 8 + q;
        const float* row = v + k * D_;
        float ss = 0.f;
        for (int i = lane; i < D_; i += 32) { float x = row[i]; ss += x * x; }
#pragma unroll
        for (int o = 16; o; o >>= 1) ss += __shfl_xor_sync(0xffffffffu, ss, o);
        if (lane == 0) sss[k] = ss;
    }
    __syncthreads();
    if (tid < 64) sinv[tid] = 1.f / fmaxf(sqrtf(sss[tid]), 1e-12f);
    __syncthreads();
    if (tid == 0) {
        float tot = 0.f;
        for (int k = 0; k < 64; k++) tot += sss[k] * sinv[k] * sinv[k];
        sbinv = 1.f / fmaxf(sqrtf(tot), 1e-12f);
    }
    __syncthreads();
    float bi = sbinv;
    for (int i = tid; i < K_ * D_; i += 256)
        out[b * (K_ * D_) + i] = v[i] * sinv[i >> 9] * bi;
}

// ---------------- launcher ----------------
extern "C" void kernel_launch(void* const* d_in, const int* in_sizes, int n_in,
                              void* d_out, int out_size) {
    const float* x       = (const float*)d_in[0];
    const float* redu_w  = (const float*)d_in[1];
    const float* redu_b  = (const float*)d_in[2];
    const float* w_x     = (const float*)d_in[3];
    const float* att_x   = (const float*)d_in[4];
    const float* att_h_w = (const float*)d_in[5];
    const float* att_b   = (const float*)d_in[6];
    const float* share_w = (const float*)d_in[7];
    const float* share_b = (const float*)d_in[8];
    const float* U_r     = (const float*)d_in[9];
    const float* U_z     = (const float*)d_in[10];
    const float* U_h     = (const float*)d_in[11];
    const float* centers = (const float*)d_in[12];
    const float* fc1_w   = (const float*)d_in[13];
    const float* fc2_w   = (const float*)d_in[14];
    float* out = (float*)d_out;

    zero_h_kernel<<<(B_ * K_ * HW_ + 255) / 256, 256>>>();
    convert_w<<<(D_ * CIN_ + 1023) / 1024, 1024>>>(redu_w);
    transpose_x<<<dim3(24, 256), 256>>>(x);
    gemm_redu_mma<<<dim3(128, 4), 256>>>(redu_b);
    gemm_wx<<<NT_, 256>>>(w_x);

    {
        float* attv_ptr = nullptr;
        cudaGetSymbolAddress((void**)&attv_ptr, g_attv);
        float* wxpb_ptr = nullptr;
        cudaGetSymbolAddress((void**)&wxpb_ptr, g_wxpb);
        conv_plain<<<NT_, 256>>>(wxpb_ptr, att_x, nullptr, attv_ptr);
    }

    for (int t = 0; t < T_; t++) {
        conv_trio<<<dim3(B_, 3), 256>>>(att_h_w, att_b, U_z, U_r);
        stats_kernel<<<(B_ * T_ * K_) / 8, 256>>>();
        fc_softmax<<<B_, 256>>>(fc1_w, fc2_w);
        wxt0_kernel<<<B_, 256>>>();
        conv_share<<<B_, 256>>>(share_w, share_b);
        conv_final<<<B_, 256>>>(U_h, t);
    }

    asum_kernel<<<B_, 256>>>();
    vlad_gemm<<<dim3(8, B_), 256>>>(centers);
    norm_kernel<<<B_, 256>>>(out);
}

// round 4
// speedup vs baseline: 2.0081x; 1.4819x over previous
#include <cuda_runtime.h>
#include <cuda_fp16.h>
#include <math.h>
#include <stdint.h>

#define B_ 32
#define T_ 8
#define K_ 64
#define D_ 512
#define CIN_ 1536
#define HW_ 64
#define NT_ 256

// ---------------- scratch (device globals; no allocation) ----------------
__device__ float g_xt [NT_ * D_ * HW_];   // (n, d, s)
__device__ float g_xtT[NT_ * HW_ * D_];   // (n, s, d)
__device__ __half g_xh[(size_t)NT_ * HW_ * CIN_]; // (col, cin) K-major fp16
__device__ __half g_wh[D_ * CIN_];        // (d, cin) K-major fp16
__device__ float g_wxpb[NT_ * K_ * HW_];
__device__ float g_attv[NT_ * K_ * HW_];
__device__ float g_hs [T_ * B_ * K_ * HW_];
__device__ float g_h   [B_ * K_ * HW_];
__device__ float g_ah  [B_ * K_ * HW_];
__device__ float g_uz  [B_ * K_ * HW_];
__device__ float g_ur  [B_ * K_ * HW_];
__device__ float g_wxt0[B_ * K_ * HW_];
__device__ float g_wxtb[B_ * K_ * HW_];
__device__ float g_zb  [B_ * K_ * HW_];
__device__ float g_rh  [B_ * K_ * HW_];
__device__ float g_asum[B_ * K_];
__device__ float g_vlad[B_ * K_ * D_];

// ---------------- utility ----------------
__global__ void zero_h_kernel() {
    int i = blockIdx.x * 256 + threadIdx.x;
    if (i < B_ * K_ * HW_) g_h[i] = 0.f;
}
__device__ __forceinline__ float sigmoidf_(float x) { return 1.f / (1.f + expf(-x)); }
__device__ __forceinline__ uint32_t smem_to_u32(const void* p) {
    uint32_t a;
    asm("{ .reg .u64 t; cvta.to.shared.u64 t, %1; cvt.u32.u64 %0, t; }"
        : "=r"(a) : "l"(p));
    return a;
}

// ---------------- convert W to fp16 ----------------
__global__ void convert_w(const float* __restrict__ W) {
    int i = blockIdx.x * 1024 + threadIdx.x;
    if (i < D_ * CIN_) g_wh[i] = __float2half(W[i]);
}

// ---------------- transpose x (n,cin,s) fp32 -> xh[(n*64+s)][cin] fp16 -------
__global__ void __launch_bounds__(256) transpose_x(const float* __restrict__ x) {
    __shared__ float sm[64 * 65];
    int n = blockIdx.y, c0 = blockIdx.x * 64;
    const float* src = x + ((size_t)n * CIN_ + c0) * 64;
    for (int i = threadIdx.x; i < 4096; i += 256) {
        int ci = i >> 6, s = i & 63;
        sm[ci * 65 + s] = src[i];
    }
    __syncthreads();
#pragma unroll
    for (int rep = 0; rep < 8; rep++) {
        int idx = rep * 256 + threadIdx.x;
        int s = idx >> 5, cp = idx & 31, ci = cp * 2;
        __half2 h = __floats2half2_rn(sm[ci * 65 + s], sm[(ci + 1) * 65 + s]);
        *(__half2*)(g_xh + ((size_t)(n * 64 + s)) * CIN_ + c0 + ci) = h;
    }
}

// ============== HMMA GEMM with cp.async double buffer + ldmatrix ============
#define GPAD 40   // halves per smem row
#define EPAD 67   // floats per epilogue smem row
#define NCH 48    // K chunks of 32
#define STAGEB (128 * GPAD * 2)   // 10240 bytes per stage buffer
#define OFF_A(st) ((st) * STAGEB)
#define OFF_B(st) (2 * STAGEB + (st) * STAGEB)

__device__ __forceinline__ void mma16816(float* c, const uint32_t* a, const uint32_t* b) {
    asm volatile(
        "mma.sync.aligned.m16n8k16.row.col.f32.f16.f16.f32 "
        "{%0,%1,%2,%3}, {%4,%5,%6,%7}, {%8,%9}, {%0,%1,%2,%3};"
        : "+f"(c[0]), "+f"(c[1]), "+f"(c[2]), "+f"(c[3])
        : "r"(a[0]), "r"(a[1]), "r"(a[2]), "r"(a[3]), "r"(b[0]), "r"(b[1]));
}
#define LDSM4(r0, r1, r2, r3, addr) \
    asm volatile("ldmatrix.sync.aligned.m8n8.x4.shared.b16 {%0,%1,%2,%3}, [%4];" \
                 : "=r"(r0), "=r"(r1), "=r"(r2), "=r"(r3) : "r"(addr))
#define CPASYNC16(saddr, gptr) \
    asm volatile("cp.async.cg.shared.global [%0], [%1], 16;" :: "r"(saddr), "l"(gptr))
#define CPCOMMIT() asm volatile("cp.async.commit_group;")
#define CPWAIT(n)  asm volatile("cp.async.wait_group %0;" :: "n"(n))

__global__ void __launch_bounds__(256) gemm_redu_mma(const float* __restrict__ bias) {
    __shared__ __align__(16) char sbuf[4 * STAGEB];   // 40960 B (>= 128*EPAD*4)
    float* sEp = (float*)sbuf;
    uint32_t sb = smem_to_u32(sbuf);

    int tid = threadIdx.x;
    int wid = tid >> 5, lane = tid & 31;
    int warp_m = wid >> 2, warp_n = wid & 3;
    int moff = warp_m * 64, noff = warp_n * 32;
    int m0 = blockIdx.x * 128, n0 = blockIdx.y * 128;
    int lr = lane >> 2, lc = (lane & 3) * 2;

    float acc[4][4][4];
#pragma unroll
    for (int i = 0; i < 4; i++)
#pragma unroll
        for (int j = 0; j < 4; j++)
#pragma unroll
            for (int q = 0; q < 4; q++) acc[i][j][q] = 0.f;

    // ldmatrix per-lane base addresses
    int lane16 = lane & 15, lanehi = lane >> 4;
    uint32_t aAddr = sb + OFF_A(0) + ((moff + lane16) * GPAD + lanehi * 8) * 2;
    int bgrp = lane >> 3;
    int brow = (lane & 7) + ((bgrp >> 1) << 3);
    int bcol = (bgrp & 1) << 3;
    uint32_t bAddr = sb + OFF_B(0) + ((noff + brow) * GPAD + bcol) * 2;

    // chunk loader: 512 A transfers + 512 B transfers of 16B
    auto load_chunk = [&](int st, int ch) {
        int k0 = ch * 32;
#pragma unroll
        for (int i = tid; i < 512; i += 256) {
            int r = i >> 2, c = i & 3;
            CPASYNC16(sb + OFF_A(st) + (uint32_t)(r * 80 + c * 16),
                      g_xh + (size_t)(m0 + r) * CIN_ + k0 + c * 8);
            CPASYNC16(sb + OFF_B(st) + (uint32_t)(r * 80 + c * 16),
                      g_wh + (size_t)(n0 + r) * CIN_ + k0 + c * 8);
        }
    };

    load_chunk(0, 0);
    CPCOMMIT();

    for (int ch = 0; ch < NCH; ch++) {
        if (ch + 1 < NCH) {
            load_chunk((ch + 1) & 1, ch + 1);
            CPCOMMIT();
            CPWAIT(1);
        } else {
            CPWAIT(0);
        }
        __syncthreads();
        uint32_t stoff = (uint32_t)((ch & 1) * STAGEB);
#pragma unroll
        for (int ks = 0; ks < 2; ks++) {
            uint32_t a[4][4], b[4][2];
#pragma unroll
            for (int mf = 0; mf < 4; mf++)
                LDSM4(a[mf][0], a[mf][1], a[mf][2], a[mf][3],
                      aAddr + stoff + (uint32_t)(mf * 16 * GPAD * 2 + ks * 32));
#pragma unroll
            for (int nfp = 0; nfp < 2; nfp++)
                LDSM4(b[2 * nfp][0], b[2 * nfp][1], b[2 * nfp + 1][0], b[2 * nfp + 1][1],
                      bAddr + stoff + (uint32_t)(nfp * 16 * GPAD * 2 + ks * 32));
#pragma unroll
            for (int mf = 0; mf < 4; mf++)
#pragma unroll
                for (int nf = 0; nf < 4; nf++)
                    mma16816(acc[mf][nf], a[mf], b[nf]);
        }
        __syncthreads();
    }

    // epilogue: two 64-d slabs through smem
#pragma unroll 1
    for (int slab = 0; slab < 2; slab++) {
        __syncthreads();
        if ((warp_n >> 1) == slab) {
            int ncol = (warp_n & 1) * 32;
#pragma unroll
            for (int mf = 0; mf < 4; mf++) {
                int row = moff + mf * 16 + lr;
#pragma unroll
                for (int nf = 0; nf < 4; nf++) {
                    int col = ncol + nf * 8 + lc;
                    sEp[row * EPAD + col]           = acc[mf][nf][0];
                    sEp[row * EPAD + col + 1]       = acc[mf][nf][1];
                    sEp[(row + 8) * EPAD + col]     = acc[mf][nf][2];
                    sEp[(row + 8) * EPAD + col + 1] = acc[mf][nf][3];
                }
            }
        }
        __syncthreads();
        int dbase = n0 + slab * 64;
#pragma unroll
        for (int idx = tid; idx < 8192; idx += 256) {
            int m = idx & 127, dn = idx >> 7;
            int col = m0 + m, nn = col >> 6, ss = col & 63;
            int d = dbase + dn;
            g_xt[(size_t)nn * (D_ * HW_) + d * 64 + ss] = sEp[m * EPAD + dn] + bias[d];
        }
#pragma unroll
        for (int idx = tid; idx < 8192; idx += 256) {
            int dn = idx & 63, m = idx >> 6;
            int col = m0 + m, nn = col >> 6, ss = col & 63;
            int d = dbase + dn;
            g_xtT[(size_t)nn * (HW_ * D_) + ss * 512 + d] = sEp[m * EPAD + dn] + bias[d];
        }
    }
}

// ---------------- GEMM 2: wxpb[n,k,s] = sum_d wx[k,d]*xt[n,d,s] ----------------
__global__ void __launch_bounds__(256) gemm_wx(const float* __restrict__ wx) {
    int n = blockIdx.x;
    __shared__ float As[16][64];
    __shared__ float Bs[16][64];
    int tid = threadIdx.x, tx = tid & 15, ty = tid >> 4;
    float acc[4][4];
#pragma unroll
    for (int i = 0; i < 4; i++)
#pragma unroll
        for (int j = 0; j < 4; j++) acc[i][j] = 0.f;
    const float* xb = g_xt + (size_t)n * (D_ * HW_);
    for (int d0 = 0; d0 < D_; d0 += 16) {
#pragma unroll
        for (int i = tid; i < 1024; i += 256) {
            int k = i >> 4, kk = i & 15;
            As[kk][k] = wx[k * D_ + d0 + kk];
        }
#pragma unroll
        for (int i = tid; i < 1024; i += 256) {
            int kk = i >> 6, s = i & 63;
            Bs[kk][s] = xb[(d0 + kk) * HW_ + s];
        }
        __syncthreads();
#pragma unroll
        for (int kk = 0; kk < 16; kk++) {
            float a[4], b[4];
#pragma unroll
            for (int i = 0; i < 4; i++) a[i] = As[kk][ty * 4 + i];
#pragma unroll
            for (int j = 0; j < 4; j++) b[j] = Bs[kk][tx * 4 + j];
#pragma unroll
            for (int i = 0; i < 4; i++)
#pragma unroll
                for (int j = 0; j < 4; j++) acc[i][j] += a[i] * b[j];
        }
        __syncthreads();
    }
#pragma unroll
    for (int i = 0; i < 4; i++)
#pragma unroll
        for (int j = 0; j < 4; j++)
            g_wxpb[n * (K_ * HW_) + (ty * 4 + i) * HW_ + tx * 4 + j] = acc[i][j];
}

// ============== conv3x3 v2: block = (image, 16-outch group), 128 threads ======
// thread = (oc_local 0..15, y 0..7), computes a full 8-px output row.
#define CPAD 96   // floats per channel in sIn (8 rows, stride 12)
#define WPAD 292  // floats per oc row in sW

__device__ __forceinline__ void conv3x3_v2(const float* __restrict__ gin,
                                           const float* __restrict__ gw, int oc0,
                                           float* sIn, float* sW, float acc[8]) {
    int tid = threadIdx.x;
    int y = tid & 7;
    int oc_l = tid >> 3;
    for (int i = tid; i < 4096; i += 128) {
        int ic = i >> 6, yy = (i >> 3) & 7, xx = i & 7;
        sIn[ic * CPAD + yy * 12 + xx] = gin[i];
    }
#pragma unroll
    for (int j = 0; j < 8; j++) acc[j] = 0.f;

#pragma unroll 1
    for (int half = 0; half < 2; half++) {
        __syncthreads();
        for (int i = tid; i < 4608; i += 128) {
            int oc = i / 288, icq = i - oc * 288;
            sW[oc * WPAD + icq] = gw[(oc0 + oc) * 576 + half * 288 + icq];
        }
        __syncthreads();
        const float* wrow = sW + oc_l * WPAD;
#pragma unroll 2
        for (int ic = 0; ic < 32; ic++) {
            const float* ip = sIn + (half * 32 + ic) * CPAD;
            float f[3][8];
#pragma unroll
            for (int r = 0; r < 3; r++) {
                int yy = y + r - 1;
                if (yy >= 0 && yy < 8) {
                    float4 v0 = *(const float4*)(ip + yy * 12);
                    float4 v1 = *(const float4*)(ip + yy * 12 + 4);
                    f[r][0] = v0.x; f[r][1] = v0.y; f[r][2] = v0.z; f[r][3] = v0.w;
                    f[r][4] = v1.x; f[r][5] = v1.y; f[r][6] = v1.z; f[r][7] = v1.w;
                } else {
#pragma unroll
                    for (int q = 0; q < 8; q++) f[r][q] = 0.f;
                }
            }
            const float* wp = wrow + ic * 9;
#pragma unroll
            for (int r = 0; r < 3; r++) {
                float w0 = wp[r * 3], w1 = wp[r * 3 + 1], w2 = wp[r * 3 + 2];
                acc[0] += w1 * f[r][0] + w2 * f[r][1];
#pragma unroll
                for (int j = 1; j < 7; j++)
                    acc[j] += w0 * f[r][j - 1] + w1 * f[r][j] + w2 * f[r][j + 1];
                acc[7] += w0 * f[r][6] + w1 * f[r][7];
            }
        }
    }
}

// plain conv: out = conv(in, w) (+bias), grid (nimg, 4)
__global__ void __launch_bounds__(128) conv_plain_v2(const float* __restrict__ in,
                                                     const float* __restrict__ w,
                                                     const float* __restrict__ bias,
                                                     float* __restrict__ out) {
    __shared__ float sIn[64 * CPAD];
    __shared__ float sW[16 * WPAD];
    int n = blockIdx.x, oc0 = blockIdx.y * 16;
    float acc[8];
    conv3x3_v2(in + n * 4096, w, oc0, sIn, sW, acc);
    int y = threadIdx.x & 7, oc = oc0 + (threadIdx.x >> 3);
    float bv = bias ? bias[oc] : 0.f;
    float* o = out + n * 4096 + oc * 64 + y * 8;
#pragma unroll
    for (int j = 0; j < 8; j++) o[j] = acc[j] + bv;
}

// trio: ah/uz/ur from h, grid (32, 3, 4)
__global__ void __launch_bounds__(128) conv_trio_v2(const float* __restrict__ w_ah,
                                                    const float* __restrict__ b_ah,
                                                    const float* __restrict__ w_uz,
                                                    const float* __restrict__ w_ur) {
    __shared__ float sIn[64 * CPAD];
    __shared__ float sW[16 * WPAD];
    int n = blockIdx.x, which = blockIdx.y, oc0 = blockIdx.z * 16;
    const float* w = (which == 0) ? w_ah : (which == 1) ? w_uz : w_ur;
    float* out = (which == 0) ? g_ah : (which == 1) ? g_uz : g_ur;
    float acc[8];
    conv3x3_v2(g_h + n * 4096, w, oc0, sIn, sW, acc);
    int y = threadIdx.x & 7, oc = oc0 + (threadIdx.x >> 3);
    float bv = (which == 0) ? b_ah[oc] : 0.f;
    float* o = out + n * 4096 + oc * 64 + y * 8;
#pragma unroll
    for (int j = 0; j < 8; j++) o[j] = acc[j] + bv;
}

// share conv + gates, grid (32, 4)
__global__ void __launch_bounds__(128) conv_share_v2(const float* __restrict__ w,
                                                     const float* __restrict__ bias) {
    __shared__ float sIn[64 * CPAD];
    __shared__ float sW[16 * WPAD];
    int n = blockIdx.x, oc0 = blockIdx.y * 16;
    float acc[8];
    conv3x3_v2(g_wxt0 + n * 4096, w, oc0, sIn, sW, acc);
    int y = threadIdx.x & 7, oc = oc0 + (threadIdx.x >> 3);
    float bv = bias[oc];
    int e = n * 4096 + oc * 64 + y * 8;
#pragma unroll
    for (int j = 0; j < 8; j++) {
        float wxt = acc[j] + bv;
        float z = sigmoidf_(wxt + g_uz[e + j]);
        float r = sigmoidf_(wxt + g_ur[e + j]);
        g_wxtb[e + j] = wxt;
        g_zb[e + j] = z;
        g_rh[e + j] = r * g_h[e + j];
    }
}

// final conv + GRU update, grid (32, 4)
__global__ void __launch_bounds__(128) conv_final_v2(const float* __restrict__ w, int t) {
    __shared__ float sIn[64 * CPAD];
    __shared__ float sW[16 * WPAD];
    int n = blockIdx.x, oc0 = blockIdx.y * 16;
    float acc[8];
    conv3x3_v2(g_rh + n * 4096, w, oc0, sIn, sW, acc);
    int y = threadIdx.x & 7, oc = oc0 + (threadIdx.x >> 3);
    int e = n * 4096 + oc * 64 + y * 8;
    float* hsp = g_hs + ((t * B_ + n) * K_ + oc) * 64 + y * 8;
#pragma unroll
    for (int j = 0; j < 8; j++) {
        float hh = tanhf(g_wxtb[e + j] + acc[j]);
        float z = g_zb[e + j];
        float hn = (1.f - z) * hh + z * g_h[e + j];
        g_h[e + j] = hn;
        hsp[j] = hn;
    }
}

// ============== fused attention: stats + fc + softmax + wxt0, per b ==========
__global__ void __launch_bounds__(256) attention_kernel(const float* __restrict__ fc1,
                                                        const float* __restrict__ fc2) {
    int b = blockIdx.x;
    __shared__ float s_ah[4096];
    __shared__ float s_mean[512], s_max[512];
    __shared__ float sh[64], se[512];
    int tid = threadIdx.x;
    int warp = tid >> 5, lane = tid & 31;

    for (int i = tid; i < 4096; i += 256) s_ah[i] = g_ah[b * 4096 + i];
    __syncthreads();

    // phase 1: mean/max over s of relu(attv + ah), 512 (t,k) pairs
#pragma unroll
    for (int q = 0; q < 64; q++) {
        int p = warp * 64 + q;                // t*64 + k
        int t = p >> 6, k = p & 63;
        const float* av = g_attv + ((b * T_ + t) * K_ + k) * 64;
        const float* ah = s_ah + k * 64;
        float v0 = fmaxf(av[lane] + ah[lane], 0.f);
        float v1 = fmaxf(av[lane + 32] + ah[lane + 32], 0.f);
        float sum = v0 + v1;
        float mx = fmaxf(v0, v1);
#pragma unroll
        for (int o = 16; o; o >>= 1) {
            sum += __shfl_xor_sync(0xffffffffu, sum, o);
            mx = fmaxf(mx, __shfl_xor_sync(0xffffffffu, mx, o));
        }
        if (lane == 0) {
            s_mean[p] = sum * (1.f / 64.f);
            s_max[p] = mx;
        }
    }
    __syncthreads();

    // phase 2: fc1 (512->32) on mean and max
#pragma unroll
    for (int q = 0; q < 8; q++) {
        int dd = warp * 8 + q;
        const float* src = (dd < 32) ? s_mean : s_max;
        const float* wrow = fc1 + (dd & 31) * 512;
        float sum = 0.f;
        for (int i = lane; i < 512; i += 32) sum += src[i] * wrow[i];
#pragma unroll
        for (int o = 16; o; o >>= 1) sum += __shfl_xor_sync(0xffffffffu, sum, o);
        if (lane == 0) sh[dd] = fmaxf(sum, 0.f);
    }
    __syncthreads();

    // fc2 (32->512), tanh, exp
#pragma unroll
    for (int rep = 0; rep < 2; rep++) {
        int o = tid + rep * 256;
        const float* w2 = fc2 + o * 32;
        float v = 0.f;
#pragma unroll
        for (int j = 0; j < 32; j++) v += w2[j] * (sh[j] + sh[j + 32]);
        se[o] = expf(tanhf(v));
    }
    __syncthreads();

    // softmax over t (in place)
    if (tid < 64) {
        float den = 0.f;
#pragma unroll
        for (int t = 0; t < T_; t++) den += se[t * 64 + tid];
        if (den == 0.f) den = 1.f;
        float inv = 1.f / den;
#pragma unroll
        for (int t = 0; t < T_; t++) se[t * 64 + tid] *= inv;
    }
    __syncthreads();

    // phase 3: wxt0 = sum_t alpha[t,k] * wxpb[b,t,k,s]
#pragma unroll
    for (int ii = 0; ii < 16; ii++) {
        int idx = tid + ii * 256;              // k*64 + s
        int k = idx >> 6;
        float accv = 0.f;
#pragma unroll
        for (int t = 0; t < T_; t++)
            accv += se[t * 64 + k] * g_wxpb[(b * T_ + t) * 4096 + idx];
        g_wxt0[b * 4096 + idx] = accv;
    }
}

// ---------------- a_sum[b,k] = sum_{t,s} hs ----------------
__global__ void __launch_bounds__(256) asum_kernel() {
    int b = blockIdx.x;
    int tid = threadIdx.x;
    int k = tid >> 2, part = tid & 3;
    float sum = 0.f;
#pragma unroll
    for (int t = 0; t < T_; t++) {
        const float* p = g_hs + ((t * B_ + b) * K_ + k) * 64 + part * 16;
#pragma unroll
        for (int s = 0; s < 16; s++) sum += p[s];
    }
    sum += __shfl_down_sync(0xffffffffu, sum, 2);
    sum += __shfl_down_sync(0xffffffffu, sum, 1);
    if (part == 0) g_asum[b * K_ + k] = sum;
}

// ---------------- VLAD GEMM ----------------
__global__ void __launch_bounds__(256) vlad_gemm(const float* __restrict__ centers) {
    int b = blockIdx.y;
    int d0 = blockIdx.x * 64;
    __shared__ float As[16][64];
    __shared__ float Bs[16][64];
    int tid = threadIdx.x, tx = tid & 15, ty = tid >> 4;
    float acc[4][4];
#pragma unroll
    for (int i = 0; i < 4; i++)
#pragma unroll
        for (int j = 0; j < 4; j++) acc[i][j] = 0.f;

    for (int ts0 = 0; ts0 < 512; ts0 += 16) {
        int t = ts0 >> 6, s0 = ts0 & 63;
        const float* hsb = g_hs + ((t * B_ + b) * K_) * 64 + s0;
        const float* xtb = g_xtT + (size_t)(b * T_ + t) * (HW_ * D_) + s0 * D_ + d0;
#pragma unroll
        for (int i = tid; i < 1024; i += 256) {
            int k = i >> 4, kk = i & 15;
            As[kk][k] = hsb[k * 64 + kk];
        }
#pragma unroll
        for (int i = tid; i < 1024; i += 256) {
            int kk = i >> 6, dd = i & 63;
            Bs[kk][dd] = xtb[kk * D_ + dd];
        }
        __syncthreads();
#pragma unroll
        for (int kk = 0; kk < 16; kk++) {
            float a[4], bb[4];
#pragma unroll
            for (int i = 0; i < 4; i++) a[i] = As[kk][ty * 4 + i];
#pragma unroll
            for (int j = 0; j < 4; j++) bb[j] = Bs[kk][tx * 4 + j];
#pragma unroll
            for (int i = 0; i < 4; i++)
#pragma unroll
                for (int j = 0; j < 4; j++) acc[i][j] += a[i] * bb[j];
        }
        __syncthreads();
    }
#pragma unroll
    for (int i = 0; i < 4; i++) {
        int k = ty * 4 + i;
        float as = g_asum[b * K_ + k];
#pragma unroll
        for (int j = 0; j < 4; j++) {
            int d = d0 + tx * 4 + j;
            g_vlad[b * (K_ * D_) + k * D_ + d] = acc[i][j] - as * centers[k * D_ + d];
        }
    }
}

// ---------------- two-level normalization ----------------
__global__ void __launch_bounds__(256) norm_kernel(float* __restrict__ out) {
    int b = blockIdx.x, tid = threadIdx.x;
    int warp = tid >> 5, lane = tid & 31;
    __shared__ float sss[64];
    __shared__ float sinv[64];
    __shared__ float sbinv;
    const float* v = g_vlad + b * (K_ * D_);
#pragma unroll
    for (int q = 0; q < 8; q++) {
        int k = warp * 8 + q;
        const float* row = v + k * D_;
        float ss = 0.f;
        for (int i = lane; i < D_; i += 32) { float x = row[i]; ss += x * x; }
#pragma unroll
        for (int o = 16; o; o >>= 1) ss += __shfl_xor_sync(0xffffffffu, ss, o);
        if (lane == 0) sss[k] = ss;
    }
    __syncthreads();
    if (tid < 64) sinv[tid] = 1.f / fmaxf(sqrtf(sss[tid]), 1e-12f);
    __syncthreads();
    if (tid == 0) {
        float tot = 0.f;
        for (int k = 0; k < 64; k++) tot += sss[k] * sinv[k] * sinv[k];
        sbinv = 1.f / fmaxf(sqrtf(tot), 1e-12f);
    }
    __syncthreads();
    float bi = sbinv;
    for (int i = tid; i < K_ * D_; i += 256)
        out[b * (K_ * D_) + i] = v[i] * sinv[i >> 9] * bi;
}

// ---------------- launcher ----------------
extern "C" void kernel_launch(void* const* d_in, const int* in_sizes, int n_in,
                              void* d_out, int out_size) {
    const float* x       = (const float*)d_in[0];
    const float* redu_w  = (const float*)d_in[1];
    const float* redu_b  = (const float*)d_in[2];
    const float* w_x     = (const float*)d_in[3];
    const float* att_x   = (const float*)d_in[4];
    const float* att_h_w = (const float*)d_in[5];
    const float* att_b   = (const float*)d_in[6];
    const float* share_w = (const float*)d_in[7];
    const float* share_b = (const float*)d_in[8];
    const float* U_r     = (const float*)d_in[9];
    const float* U_z     = (const float*)d_in[10];
    const float* U_h     = (const float*)d_in[11];
    const float* centers = (const float*)d_in[12];
    const float* fc1_w   = (const float*)d_in[13];
    const float* fc2_w   = (const float*)d_in[14];
    float* out = (float*)d_out;

    zero_h_kernel<<<(B_ * K_ * HW_ + 255) / 256, 256>>>();
    convert_w<<<(D_ * CIN_ + 1023) / 1024, 1024>>>(redu_w);
    transpose_x<<<dim3(24, 256), 256>>>(x);
    gemm_redu_mma<<<dim3(128, 4), 256>>>(redu_b);
    gemm_wx<<<NT_, 256>>>(w_x);

    {
        float* attv_ptr = nullptr;
        cudaGetSymbolAddress((void**)&attv_ptr, g_attv);
        float* wxpb_ptr = nullptr;
        cudaGetSymbolAddress((void**)&wxpb_ptr, g_wxpb);
        conv_plain_v2<<<dim3(NT_, 4), 128>>>(wxpb_ptr, att_x, nullptr, attv_ptr);
    }

    for (int t = 0; t < T_; t++) {
        conv_trio_v2<<<dim3(B_, 3, 4), 128>>>(att_h_w, att_b, U_z, U_r);
        attention_kernel<<<B_, 256>>>(fc1_w, fc2_w);
        conv_share_v2<<<dim3(B_, 4), 128>>>(share_w, share_b);
        conv_final_v2<<<dim3(B_, 4), 128>>>(U_h, t);
    }

    asum_kernel<<<B_, 256>>>();
    vlad_gemm<<<dim3(8, B_), 256>>>(centers);
    norm_kernel<<<B_, 256>>>(out);
}